// round 8
// baseline (speedup 1.0000x reference)
#include <cuda_runtime.h>

#define B_  16
#define T_  128
#define H_  1024
#define FH  4096
#define V_  32000
#define M_  2048   // B_*T_

// ---------------- device scratch (allocation-free) ----------------
__device__ float g_Pre[M_ * FH];   // 32 MB: X@Wx2^T + b2, rows m = t*16+b
__device__ float g_Hs [M_ * H_];   //  8 MB: emitted h, rows m = t*16+b
__device__ float g_c  [B_ * H_];   // cell state,   [b][k]
__device__ float g_h  [B_ * H_];   // hidden state, [b][k]

__device__ __forceinline__ float sigf(float x) { return 1.f / (1.f + __expf(-x)); }

// ---------------- packed fp32x2 helpers (sm_100+) ----------------
__device__ __forceinline__ unsigned long long pack2(float x, float y) {
    unsigned long long r;
    asm("mov.b64 %0, {%1, %2};" : "=l"(r) : "f"(x), "f"(y));
    return r;
}
__device__ __forceinline__ void fma2(unsigned long long& d,
                                     unsigned long long a, unsigned long long b) {
    asm("fma.rn.f32x2 %0, %1, %2, %0;" : "+l"(d) : "l"(a), "l"(b));
}
__device__ __forceinline__ float2 unpk(unsigned long long v) {
    float2 r;
    asm("mov.b64 {%0, %1}, %2;" : "=f"(r.x), "=f"(r.y) : "l"(v));
    return r;
}

// =====================================================================
// Tiled 128x128x16 SGEMM, C = A @ B^T + bias. 256 threads, 8x8 microtile,
// packed f32x2 inner product (2 FMA per fma-pipe slot).
//  GATHER : A row m is W_emb[idx[b*T_+t]] (m = t*16+b); writes g_Pre.
//  SOFTMAX: A = g_Hs; epilogue softmaxes each 16-row batch group (one
//           group per warp) and writes out[b][t][v].
// =====================================================================
template<bool GATHER, bool SOFTMAX>
__global__ __launch_bounds__(256, 2)
void sgemm(const float* __restrict__ A, const float* __restrict__ Bw,
           const float* __restrict__ bias, const int* __restrict__ idx,
           float* __restrict__ C)
{
    __shared__ alignas(16) float As[16][132];
    __shared__ alignas(16) float Bs[16][132];

    const int tid = threadIdx.x;
    const int ty  = tid >> 4, tx = tid & 15;
    const int m0  = blockIdx.x * 128;
    const int n0  = blockIdx.y * 128;

    const int r  = tid >> 1;     // load-role row
    const int lq = tid & 1;

    const float* arow;
    if (GATHER) {
        int m = m0 + r;
        int t = m >> 4, b = m & 15;
        arow = A + (size_t)idx[b * T_ + t] * H_;
    } else {
        arow = g_Hs + (size_t)(m0 + r) * H_;
    }
    const float* brow = Bw + (size_t)(n0 + r) * H_;

    unsigned long long acc2[8][4];
#pragma unroll
    for (int i = 0; i < 8; i++)
#pragma unroll
        for (int j = 0; j < 4; j++) acc2[i][j] = 0ull;

    for (int k0 = 0; k0 < H_; k0 += 16) {
#pragma unroll
        for (int p = 0; p < 2; p++) {
            int q = lq + 2 * p;  // 0..3
            float4 a4 = *reinterpret_cast<const float4*>(arow + k0 + q * 4);
            float4 b4 = *reinterpret_cast<const float4*>(brow + k0 + q * 4);
            As[q*4+0][r] = a4.x; As[q*4+1][r] = a4.y;
            As[q*4+2][r] = a4.z; As[q*4+3][r] = a4.w;
            Bs[q*4+0][r] = b4.x; Bs[q*4+1][r] = b4.y;
            Bs[q*4+2][r] = b4.z; Bs[q*4+3][r] = b4.w;
        }
        __syncthreads();
#pragma unroll
        for (int kk = 0; kk < 16; kk++) {
            float a[8];
            *reinterpret_cast<float4*>(&a[0]) = *reinterpret_cast<float4*>(&As[kk][ty*8]);
            *reinterpret_cast<float4*>(&a[4]) = *reinterpret_cast<float4*>(&As[kk][ty*8+4]);
            ulonglong2 u0 = *reinterpret_cast<ulonglong2*>(&Bs[kk][tx*8]);
            ulonglong2 u1 = *reinterpret_cast<ulonglong2*>(&Bs[kk][tx*8+4]);
            unsigned long long bp[4] = {u0.x, u0.y, u1.x, u1.y};
#pragma unroll
            for (int i = 0; i < 8; i++) {
                unsigned long long ap = pack2(a[i], a[i]);
#pragma unroll
                for (int j = 0; j < 4; j++) fma2(acc2[i][j], ap, bp[j]);
            }
        }
        __syncthreads();
    }

    // unpack to scalar accumulators
    float acc[8][8];
#pragma unroll
    for (int i = 0; i < 8; i++)
#pragma unroll
        for (int j = 0; j < 4; j++) {
            float2 p = unpk(acc2[i][j]);
            acc[i][2*j] = p.x; acc[i][2*j+1] = p.y;
        }

    float bs[8];
#pragma unroll
    for (int j = 0; j < 8; j++) bs[j] = bias[n0 + tx * 8 + j];

    if (!SOFTMAX) {
#pragma unroll
        for (int i = 0; i < 8; i++) {
            float* crow = g_Pre + (size_t)(m0 + ty * 8 + i) * FH + n0 + tx * 8;
            float4 o0, o1;
            o0.x = acc[i][0]+bs[0]; o0.y = acc[i][1]+bs[1];
            o0.z = acc[i][2]+bs[2]; o0.w = acc[i][3]+bs[3];
            o1.x = acc[i][4]+bs[4]; o1.y = acc[i][5]+bs[5];
            o1.z = acc[i][6]+bs[6]; o1.w = acc[i][7]+bs[7];
            *reinterpret_cast<float4*>(crow)     = o0;
            *reinterpret_cast<float4*>(crow + 4) = o1;
        }
    } else {
#pragma unroll
        for (int i = 0; i < 8; i++)
#pragma unroll
            for (int j = 0; j < 8; j++) acc[i][j] += bs[j];
#pragma unroll
        for (int j = 0; j < 8; j++) {
            float mx = acc[0][j];
#pragma unroll
            for (int i = 1; i < 8; i++) mx = fmaxf(mx, acc[i][j]);
            mx = fmaxf(mx, __shfl_xor_sync(0xffffffffu, mx, 16));
            float s = 0.f;
#pragma unroll
            for (int i = 0; i < 8; i++) { acc[i][j] = __expf(acc[i][j] - mx); s += acc[i][j]; }
            s += __shfl_xor_sync(0xffffffffu, s, 16);
            float inv = 1.f / s;
#pragma unroll
            for (int i = 0; i < 8; i++) acc[i][j] *= inv;
        }
        const int tcol = (m0 >> 4) + (tid >> 5);   // t, constant per warp
#pragma unroll
        for (int i = 0; i < 8; i++) {
            int b = ((ty & 1) << 3) + i;
            float* orow = C + (size_t)b * (T_ * (size_t)V_) + (size_t)tcol * V_ + n0 + tx * 8;
            float4 o0, o1;
            o0.x = acc[i][0]; o0.y = acc[i][1]; o0.z = acc[i][2]; o0.w = acc[i][3];
            o1.x = acc[i][4]; o1.y = acc[i][5]; o1.z = acc[i][6]; o1.w = acc[i][7];
            *reinterpret_cast<float4*>(orow)     = o0;
            *reinterpret_cast<float4*>(orow + 4) = o1;
        }
    }
}

// =====================================================================
// Fused LSTM step, register-pressure-fixed layout.
// Grid 256 x 256 threads (8 warps). CTA owns 4 hidden indices j.
// Warp w: j = j0 + (w>>1); gate-pair gp = (w&1) -> gates {2gp, 2gp+1}
// (rows g*1024+j of Wh). acc2[2][16] packed = 64 regs. Lanes span K.
// Gate pairs meet in smem; 64 threads apply the faithful-quirk update:
//   A = tanh(pre + rec); f,i,o = sig(A.), g = tanh(A.)
//   c_new = f*c_old + g*i; h_next = o*tanh(c_OLD); Hs[t+1] = h_next.
// =====================================================================
__global__ __launch_bounds__(256, 2)
void lstm_step(const float* __restrict__ Wh, int t)
{
    __shared__ alignas(16) float hs[16][512];
    __shared__ float gs[4][4][16];          // [jj][gate][b]

    const int tid = threadIdx.x;
    const int w   = tid >> 5, l = tid & 31;
    const int jj  = w >> 1;
    const int j   = blockIdx.x * 4 + jj;
    const int g0  = (w & 1) * 2;            // first gate of this warp's pair

    const float* whr0 = Wh + (size_t)((g0    ) * H_ + j) * H_;
    const float* whr1 = Wh + (size_t)((g0 + 1) * H_ + j) * H_;

    unsigned long long acc2[2][16];
#pragma unroll
    for (int g = 0; g < 2; g++)
#pragma unroll
        for (int b = 0; b < 16; b++) acc2[g][b] = 0ull;

    for (int half = 0; half < 2; half++) {
#pragma unroll
        for (int p = 0; p < 8; p++) {
            int e  = p * 256 + tid;     // float4 index, 0..2047
            int b  = e >> 7;
            int c4 = e & 127;
            *reinterpret_cast<float4*>(&hs[b][c4 * 4]) =
                *reinterpret_cast<const float4*>(g_h + b * H_ + half * 512 + c4 * 4);
        }
        __syncthreads();
#pragma unroll
        for (int it = 0; it < 4; it++) {
            int kl = it * 128 + l * 4;
            int k  = half * 512 + kl;
            float4 wa = *reinterpret_cast<const float4*>(whr0 + k);
            float4 wb = *reinterpret_cast<const float4*>(whr1 + k);
            unsigned long long wp0a = pack2(wa.x, wa.y), wp0b = pack2(wa.z, wa.w);
            unsigned long long wp1a = pack2(wb.x, wb.y), wp1b = pack2(wb.z, wb.w);
#pragma unroll
            for (int b = 0; b < 16; b++) {
                float4 h4 = *reinterpret_cast<float4*>(&hs[b][kl]);
                unsigned long long hp0 = pack2(h4.x, h4.y);
                unsigned long long hp1 = pack2(h4.z, h4.w);
                fma2(acc2[0][b], wp0a, hp0);
                fma2(acc2[0][b], wp0b, hp1);
                fma2(acc2[1][b], wp1a, hp0);
                fma2(acc2[1][b], wp1b, hp1);
            }
        }
        __syncthreads();
    }

    // cross-lane reduce (lanes hold disjoint K partials); lanes<16 publish
#pragma unroll
    for (int g = 0; g < 2; g++)
#pragma unroll
        for (int b = 0; b < 16; b++) {
            float2 p = unpk(acc2[g][b]);
            float s = p.x + p.y;
#pragma unroll
            for (int d = 16; d >= 1; d >>= 1)
                s += __shfl_xor_sync(0xffffffffu, s, d);
            if (l == b) gs[jj][g0 + g][b] = s;
        }
    __syncthreads();

    if (tid < 64) {
        const int b  = tid & 15;
        const int jq = tid >> 4;           // 0..3
        const int jn = blockIdx.x * 4 + jq;
        const float* pre = g_Pre + (size_t)(t * 16 + b) * FH;
        float Af = tanhf(gs[jq][0][b] + pre[jn]);
        float Ag = tanhf(gs[jq][1][b] + pre[1024 + jn]);
        float Ai = tanhf(gs[jq][2][b] + pre[2048 + jn]);
        float Ao = tanhf(gs[jq][3][b] + pre[3072 + jn]);
        float f  = sigf(Af);
        float gg = tanhf(Ag);
        float ii = sigf(Ai);
        float oo = sigf(Ao);
        int e = b * H_ + jn;
        float cold = g_c[e];
        g_c[e] = f * cold + gg * ii;
        float hn = oo * tanhf(cold);
        g_h[e] = hn;
        g_Hs[(size_t)(t + 1) * (B_ * H_) + e] = hn;
    }
}

__global__ void lstm_init()
{
    int e = blockIdx.x * blockDim.x + threadIdx.x;
    if (e < B_ * H_) { g_c[e] = 0.f; g_h[e] = 0.f; g_Hs[e] = 0.f; }
}

// =====================================================================
extern "C" void kernel_launch(void* const* d_in, const int* in_sizes, int n_in,
                              void* d_out, int out_size)
{
    const int*   idx   = (const int*)  d_in[0];
    const float* W_emb = (const float*)d_in[1];
    const float* Wx2   = (const float*)d_in[2];
    const float* Wh2   = (const float*)d_in[3];
    const float* b2    = (const float*)d_in[4];
    const float* Wa    = (const float*)d_in[5];
    const float* ba    = (const float*)d_in[6];
    float* out = (float*)d_out;
    (void)in_sizes; (void)n_in; (void)out_size;

    lstm_init<<<64, 256>>>();

    // Pre = gather(W_emb, idx) @ Wx2^T + b2   (rows m = t*16+b)
    sgemm<true, false><<<dim3(16, FH / 128), 256>>>(W_emb, Wx2, b2, idx, out);

    // 127 fused recurrent steps (step 127's update is never consumed)
    for (int t = 0; t < T_ - 1; t++)
        lstm_step<<<256, 256>>>(Wh2, t);

    // V = Hs @ Wa^T + ba, fused softmax over batch axis -> out[b][t][v]
    sgemm<false, true><<<dim3(16, V_ / 128), 256>>>(W_emb, Wa, ba, idx, out);
}

// round 9
// speedup vs baseline: 1.0313x; 1.0313x over previous
#include <cuda_runtime.h>

#define B_  16
#define T_  128
#define H_  1024
#define FH  4096
#define V_  32000
#define M_  2048   // B_*T_

// ---------------- device scratch (allocation-free) ----------------
__device__ float g_Pre[M_ * FH];      // 32 MB: X@Wx2^T + b2, rows m = t*16+b
__device__ float g_Hs [M_ * H_];      //  8 MB: emitted h, rows m = t*16+b
__device__ float g_hbuf[2][B_ * H_];  // double-buffered h for the recurrence
__device__ unsigned int g_bar;        // grid barrier counter (monotonic per launch)

__device__ __forceinline__ float sigf(float x) { return 1.f / (1.f + __expf(-x)); }

// ---------------- packed fp32x2 helpers (sm_100+) ----------------
__device__ __forceinline__ unsigned long long pack2(float x, float y) {
    unsigned long long r;
    asm("mov.b64 %0, {%1, %2};" : "=l"(r) : "f"(x), "f"(y));
    return r;
}
__device__ __forceinline__ void fma2(unsigned long long& d,
                                     unsigned long long a, unsigned long long b) {
    asm("fma.rn.f32x2 %0, %1, %2, %0;" : "+l"(d) : "l"(a), "l"(b));
}
__device__ __forceinline__ float2 unpk(unsigned long long v) {
    float2 r;
    asm("mov.b64 {%0, %1}, %2;" : "=f"(r.x), "=f"(r.y) : "l"(v));
    return r;
}

// =====================================================================
// Tiled 128x128x16 SGEMM, C = A @ B^T + bias. 256 threads, 8x8 microtile,
// packed f32x2 inner product.
//  GATHER : A row m is W_emb[idx[b*T_+t]] (m = t*16+b); writes g_Pre.
//  SOFTMAX: A = g_Hs; epilogue softmaxes each 16-row batch group (one
//           group per warp) and writes out[b][t][v].
// =====================================================================
template<bool GATHER, bool SOFTMAX>
__global__ __launch_bounds__(256, 2)
void sgemm(const float* __restrict__ A, const float* __restrict__ Bw,
           const float* __restrict__ bias, const int* __restrict__ idx,
           float* __restrict__ C)
{
    __shared__ alignas(16) float As[16][132];
    __shared__ alignas(16) float Bs[16][132];

    const int tid = threadIdx.x;
    const int ty  = tid >> 4, tx = tid & 15;
    const int m0  = blockIdx.x * 128;
    const int n0  = blockIdx.y * 128;

    const int r  = tid >> 1;     // load-role row
    const int lq = tid & 1;

    const float* arow;
    if (GATHER) {
        int m = m0 + r;
        int t = m >> 4, b = m & 15;
        arow = A + (size_t)idx[b * T_ + t] * H_;
    } else {
        arow = g_Hs + (size_t)(m0 + r) * H_;
    }
    const float* brow = Bw + (size_t)(n0 + r) * H_;

    unsigned long long acc2[8][4];
#pragma unroll
    for (int i = 0; i < 8; i++)
#pragma unroll
        for (int j = 0; j < 4; j++) acc2[i][j] = 0ull;

    for (int k0 = 0; k0 < H_; k0 += 16) {
#pragma unroll
        for (int p = 0; p < 2; p++) {
            int q = lq + 2 * p;  // 0..3
            float4 a4 = *reinterpret_cast<const float4*>(arow + k0 + q * 4);
            float4 b4 = *reinterpret_cast<const float4*>(brow + k0 + q * 4);
            As[q*4+0][r] = a4.x; As[q*4+1][r] = a4.y;
            As[q*4+2][r] = a4.z; As[q*4+3][r] = a4.w;
            Bs[q*4+0][r] = b4.x; Bs[q*4+1][r] = b4.y;
            Bs[q*4+2][r] = b4.z; Bs[q*4+3][r] = b4.w;
        }
        __syncthreads();
#pragma unroll
        for (int kk = 0; kk < 16; kk++) {
            float a[8];
            *reinterpret_cast<float4*>(&a[0]) = *reinterpret_cast<float4*>(&As[kk][ty*8]);
            *reinterpret_cast<float4*>(&a[4]) = *reinterpret_cast<float4*>(&As[kk][ty*8+4]);
            ulonglong2 u0 = *reinterpret_cast<ulonglong2*>(&Bs[kk][tx*8]);
            ulonglong2 u1 = *reinterpret_cast<ulonglong2*>(&Bs[kk][tx*8+4]);
            unsigned long long bp[4] = {u0.x, u0.y, u1.x, u1.y};
#pragma unroll
            for (int i = 0; i < 8; i++) {
                unsigned long long ap = pack2(a[i], a[i]);
#pragma unroll
                for (int j = 0; j < 4; j++) fma2(acc2[i][j], ap, bp[j]);
            }
        }
        __syncthreads();
    }

    float acc[8][8];
#pragma unroll
    for (int i = 0; i < 8; i++)
#pragma unroll
        for (int j = 0; j < 4; j++) {
            float2 p = unpk(acc2[i][j]);
            acc[i][2*j] = p.x; acc[i][2*j+1] = p.y;
        }

    float bs[8];
#pragma unroll
    for (int j = 0; j < 8; j++) bs[j] = bias[n0 + tx * 8 + j];

    if (!SOFTMAX) {
#pragma unroll
        for (int i = 0; i < 8; i++) {
            float* crow = g_Pre + (size_t)(m0 + ty * 8 + i) * FH + n0 + tx * 8;
            float4 o0, o1;
            o0.x = acc[i][0]+bs[0]; o0.y = acc[i][1]+bs[1];
            o0.z = acc[i][2]+bs[2]; o0.w = acc[i][3]+bs[3];
            o1.x = acc[i][4]+bs[4]; o1.y = acc[i][5]+bs[5];
            o1.z = acc[i][6]+bs[6]; o1.w = acc[i][7]+bs[7];
            *reinterpret_cast<float4*>(crow)     = o0;
            *reinterpret_cast<float4*>(crow + 4) = o1;
        }
    } else {
#pragma unroll
        for (int i = 0; i < 8; i++)
#pragma unroll
            for (int j = 0; j < 8; j++) acc[i][j] += bs[j];
#pragma unroll
        for (int j = 0; j < 8; j++) {
            float mx = acc[0][j];
#pragma unroll
            for (int i = 1; i < 8; i++) mx = fmaxf(mx, acc[i][j]);
            mx = fmaxf(mx, __shfl_xor_sync(0xffffffffu, mx, 16));
            float s = 0.f;
#pragma unroll
            for (int i = 0; i < 8; i++) { acc[i][j] = __expf(acc[i][j] - mx); s += acc[i][j]; }
            s += __shfl_xor_sync(0xffffffffu, s, 16);
            float inv = 1.f / s;
#pragma unroll
            for (int i = 0; i < 8; i++) acc[i][j] *= inv;
        }
        const int tcol = (m0 >> 4) + (tid >> 5);   // t, constant per warp
#pragma unroll
        for (int i = 0; i < 8; i++) {
            int b = ((ty & 1) << 3) + i;
            float* orow = C + (size_t)b * (T_ * (size_t)V_) + (size_t)tcol * V_ + n0 + tx * 8;
            float4 o0, o1;
            o0.x = acc[i][0]; o0.y = acc[i][1]; o0.z = acc[i][2]; o0.w = acc[i][3];
            o1.x = acc[i][4]; o1.y = acc[i][5]; o1.z = acc[i][6]; o1.w = acc[i][7];
            *reinterpret_cast<float4*>(orow)     = o0;
            *reinterpret_cast<float4*>(orow + 4) = o1;
        }
    }
}

// =====================================================================
// Persistent LSTM recurrence: ONE kernel runs all 127 steps.
// Grid 128 CTAs x 512 threads, 1 CTA/SM (all resident -> safe barrier).
// CTA owns 8 hidden indices j (and all 4 gates). Cell state lives in smem.
// Warp = (jj 0..7, batch-octet o 0..1); lanes span the FULL K=1024
// (k = l*4 + i*128) so each warp produces complete dot products.
// Inner: 1 h-LDS.128 feeds 4 gates x 2 fma2 (8:1 fma:LDS).
// h exchanged via double-buffered global (ldcg staging, STG publish),
// grid barrier = monotonic atomic counter (reset each launch by lstm_init).
// Quirks: A=tanh(pre); f,i,o=sig, g=tanh; c=f*c+g*i; h_next=o*tanh(c_OLD);
// Hs[t+1]=h_next (Hs[0] zeroed).
// =====================================================================
__global__ __launch_bounds__(512, 1)
void lstm_persist(const float* __restrict__ Wh)
{
    __shared__ alignas(16) float hs[B_][512];   // half of h (k-half staged)
    __shared__ float gs[8][4][16];              // [jj][gate][b]
    __shared__ float cs[16][8];                 // cell state [b][jq]

    const int tid = threadIdx.x;
    const int w   = tid >> 5, l = tid & 31;
    const int jj  = w & 7;
    const int o   = w >> 3;                     // batch octet 0/1
    const int j   = blockIdx.x * 8 + jj;

    if (tid < 128) cs[tid >> 3][tid & 7] = 0.f;

    const ulonglong2* wrow[4];
#pragma unroll
    for (int g = 0; g < 4; g++)
        wrow[g] = reinterpret_cast<const ulonglong2*>(Wh + (size_t)(g * H_ + j) * H_);

    for (int t = 0; t < T_ - 1; t++) {
        unsigned long long acc[4][8];
#pragma unroll
        for (int g = 0; g < 4; g++)
#pragma unroll
            for (int b = 0; b < 8; b++) acc[g][b] = 0ull;

        const float4* hsrc = reinterpret_cast<const float4*>(g_hbuf[t & 1]);

        for (int half = 0; half < 2; half++) {
            // stage k-half of h: 32 KB, L1-bypassing (cross-SM freshness)
#pragma unroll
            for (int p = 0; p < 4; p++) {
                int e  = p * 512 + tid;          // 0..2047 float4 idx in half
                int b  = e >> 7;                 // 128 float4 per row-half
                int c4 = e & 127;
                float4 v = __ldcg(hsrc + (size_t)b * 256 + half * 128 + c4);
                *reinterpret_cast<float4*>(&hs[b][c4 * 4]) = v;
            }
            __syncthreads();
#pragma unroll
            for (int i = 0; i < 4; i++) {
                int kl = l * 4 + i * 128;              // local k in half
                int kg = half * 512 + kl;              // global k
                ulonglong2 wg[4];
#pragma unroll
                for (int g = 0; g < 4; g++) wg[g] = wrow[g][kg >> 2];
#pragma unroll
                for (int b = 0; b < 8; b++) {
                    ulonglong2 h2 = *reinterpret_cast<const ulonglong2*>(&hs[o * 8 + b][kl]);
#pragma unroll
                    for (int g = 0; g < 4; g++) {
                        fma2(acc[g][b], wg[g].x, h2.x);
                        fma2(acc[g][b], wg[g].y, h2.y);
                    }
                }
            }
            __syncthreads();
        }

        // full butterfly per (gate, b); publish to gs by designated lane
#pragma unroll
        for (int g = 0; g < 4; g++)
#pragma unroll
            for (int b = 0; b < 8; b++) {
                float2 p2 = unpk(acc[g][b]);
                float s = p2.x + p2.y;
#pragma unroll
                for (int d = 16; d >= 1; d >>= 1)
                    s += __shfl_xor_sync(0xffffffffu, s, d);
                if (l == g * 8 + b) gs[jj][g][o * 8 + b] = s;
            }
        __syncthreads();

        // gate nonlinearities + state update (128 threads: b x jq)
        if (tid < 128) {
            const int bq = tid >> 3, jq = tid & 7;
            const int jn = blockIdx.x * 8 + jq;
            const float* pre = g_Pre + (size_t)(t * 16 + bq) * FH;
            float Af = tanhf(gs[jq][0][bq] + pre[jn]);
            float Ag = tanhf(gs[jq][1][bq] + pre[1024 + jn]);
            float Ai = tanhf(gs[jq][2][bq] + pre[2048 + jn]);
            float Ao = tanhf(gs[jq][3][bq] + pre[3072 + jn]);
            float f  = sigf(Af);
            float gg = tanhf(Ag);
            float ii = sigf(Ai);
            float oo = sigf(Ao);
            float cold = cs[bq][jq];
            cs[bq][jq] = f * cold + gg * ii;
            float hn = oo * tanhf(cold);
            g_hbuf[(t + 1) & 1][bq * H_ + jn] = hn;
            g_Hs[(size_t)(t + 1) * (B_ * H_) + bq * H_ + jn] = hn;
        }

        // grid barrier: publish h, then everyone waits
        __threadfence();
        __syncthreads();
        if (tid == 0) {
            atomicAdd(&g_bar, 1u);
            unsigned int target = 128u * (unsigned int)(t + 1);
            volatile unsigned int* vb = &g_bar;
            while (*vb < target) __nanosleep(32);
        }
        __syncthreads();
        __threadfence();
    }
}

__global__ void lstm_init()
{
    int e = blockIdx.x * blockDim.x + threadIdx.x;   // 0..32767
    if (e == 0) g_bar = 0u;
    reinterpret_cast<float*>(g_hbuf)[e] = 0.f;       // both h buffers
    if (e < B_ * H_) g_Hs[e] = 0.f;                  // Hs[0]
}

// =====================================================================
extern "C" void kernel_launch(void* const* d_in, const int* in_sizes, int n_in,
                              void* d_out, int out_size)
{
    const int*   idx   = (const int*)  d_in[0];
    const float* W_emb = (const float*)d_in[1];
    const float* Wx2   = (const float*)d_in[2];
    const float* Wh2   = (const float*)d_in[3];
    const float* b2    = (const float*)d_in[4];
    const float* Wa    = (const float*)d_in[5];
    const float* ba    = (const float*)d_in[6];
    float* out = (float*)d_out;
    (void)in_sizes; (void)n_in; (void)out_size;

    lstm_init<<<128, 256>>>();

    // Pre = gather(W_emb, idx) @ Wx2^T + b2   (rows m = t*16+b)
    sgemm<true, false><<<dim3(16, FH / 128), 256>>>(W_emb, Wx2, b2, idx, out);

    // whole recurrence in ONE persistent kernel (127 steps + grid barriers)
    lstm_persist<<<128, 512>>>(Wh2);

    // V = Hs @ Wa^T + ba, fused softmax over batch axis -> out[b][t][v]
    sgemm<false, true><<<dim3(16, V_ / 128), 256>>>(W_emb, Wa, ba, idx, out);
}

// round 14
// speedup vs baseline: 1.0461x; 1.0143x over previous
#include <cuda_runtime.h>
#include <cstdint>

#define B_  16
#define T_  128
#define H_  1024
#define FH  4096
#define V_  32000
#define M_  2048   // B_*T_

// ---------------- device scratch (allocation-free) ----------------
__device__ float g_Pre[M_ * FH];      // 32 MB: X@Wx2^T + b2, rows m = t*16+b
__device__ float g_Hs [M_ * H_];      //  8 MB: emitted h, rows m = t*16+b
__device__ float g_hbuf[2][B_ * H_];  // double-buffered h (L2-only traffic)
__device__ unsigned int g_bar;        // grid barrier counter

__device__ __forceinline__ float sigf(float x) { return 1.f / (1.f + __expf(-x)); }

// ---------------- packed fp32x2 helpers ----------------
__device__ __forceinline__ unsigned long long pack2(float x, float y) {
    unsigned long long r;
    asm("mov.b64 %0, {%1, %2};" : "=l"(r) : "f"(x), "f"(y));
    return r;
}
__device__ __forceinline__ void fma2(unsigned long long& d,
                                     unsigned long long a, unsigned long long b) {
    asm("fma.rn.f32x2 %0, %1, %2, %0;" : "+l"(d) : "l"(a), "l"(b));
}
__device__ __forceinline__ float2 unpk(unsigned long long v) {
    float2 r;
    asm("mov.b64 {%0, %1}, %2;" : "=f"(r.x), "=f"(r.y) : "l"(v));
    return r;
}

// =====================================================================
// Tiled 128x128x16 SGEMM, C = A @ B^T + bias. 256 threads, 8x8 microtile,
// packed f32x2 inner product. (R9-proven)
//  GATHER : A row m is W_emb[idx[b*T_+t]] (m = t*16+b); writes g_Pre.
//  SOFTMAX: A = g_Hs; epilogue softmaxes each 16-row batch group (one
//           group per warp) and writes out[b][t][v].
// =====================================================================
template<bool GATHER, bool SOFTMAX>
__global__ __launch_bounds__(256, 2)
void sgemm(const float* __restrict__ A, const float* __restrict__ Bw,
           const float* __restrict__ bias, const int* __restrict__ idx,
           float* __restrict__ C)
{
    __shared__ alignas(16) float As[16][132];
    __shared__ alignas(16) float Bs[16][132];

    const int tid = threadIdx.x;
    const int ty  = tid >> 4, tx = tid & 15;
    const int m0  = blockIdx.x * 128;
    const int n0  = blockIdx.y * 128;

    const int r  = tid >> 1;
    const int lq = tid & 1;

    const float* arow;
    if (GATHER) {
        int m = m0 + r;
        int t = m >> 4, b = m & 15;
        arow = A + (size_t)idx[b * T_ + t] * H_;
    } else {
        arow = g_Hs + (size_t)(m0 + r) * H_;
    }
    const float* brow = Bw + (size_t)(n0 + r) * H_;

    unsigned long long acc2[8][4];
#pragma unroll
    for (int i = 0; i < 8; i++)
#pragma unroll
        for (int j = 0; j < 4; j++) acc2[i][j] = 0ull;

    for (int k0 = 0; k0 < H_; k0 += 16) {
#pragma unroll
        for (int p = 0; p < 2; p++) {
            int q = lq + 2 * p;
            float4 a4 = *reinterpret_cast<const float4*>(arow + k0 + q * 4);
            float4 b4 = *reinterpret_cast<const float4*>(brow + k0 + q * 4);
            As[q*4+0][r] = a4.x; As[q*4+1][r] = a4.y;
            As[q*4+2][r] = a4.z; As[q*4+3][r] = a4.w;
            Bs[q*4+0][r] = b4.x; Bs[q*4+1][r] = b4.y;
            Bs[q*4+2][r] = b4.z; Bs[q*4+3][r] = b4.w;
        }
        __syncthreads();
#pragma unroll
        for (int kk = 0; kk < 16; kk++) {
            float a[8];
            *reinterpret_cast<float4*>(&a[0]) = *reinterpret_cast<float4*>(&As[kk][ty*8]);
            *reinterpret_cast<float4*>(&a[4]) = *reinterpret_cast<float4*>(&As[kk][ty*8+4]);
            ulonglong2 u0 = *reinterpret_cast<ulonglong2*>(&Bs[kk][tx*8]);
            ulonglong2 u1 = *reinterpret_cast<ulonglong2*>(&Bs[kk][tx*8+4]);
            unsigned long long bp[4] = {u0.x, u0.y, u1.x, u1.y};
#pragma unroll
            for (int i = 0; i < 8; i++) {
                unsigned long long ap = pack2(a[i], a[i]);
#pragma unroll
                for (int j = 0; j < 4; j++) fma2(acc2[i][j], ap, bp[j]);
            }
        }
        __syncthreads();
    }

    float acc[8][8];
#pragma unroll
    for (int i = 0; i < 8; i++)
#pragma unroll
        for (int j = 0; j < 4; j++) {
            float2 p = unpk(acc2[i][j]);
            acc[i][2*j] = p.x; acc[i][2*j+1] = p.y;
        }

    float bs[8];
#pragma unroll
    for (int j = 0; j < 8; j++) bs[j] = bias[n0 + tx * 8 + j];

    if (!SOFTMAX) {
#pragma unroll
        for (int i = 0; i < 8; i++) {
            float* crow = g_Pre + (size_t)(m0 + ty * 8 + i) * FH + n0 + tx * 8;
            float4 o0, o1;
            o0.x = acc[i][0]+bs[0]; o0.y = acc[i][1]+bs[1];
            o0.z = acc[i][2]+bs[2]; o0.w = acc[i][3]+bs[3];
            o1.x = acc[i][4]+bs[4]; o1.y = acc[i][5]+bs[5];
            o1.z = acc[i][6]+bs[6]; o1.w = acc[i][7]+bs[7];
            *reinterpret_cast<float4*>(crow)     = o0;
            *reinterpret_cast<float4*>(crow + 4) = o1;
        }
    } else {
#pragma unroll
        for (int i = 0; i < 8; i++)
#pragma unroll
            for (int j = 0; j < 8; j++) acc[i][j] += bs[j];
#pragma unroll
        for (int j = 0; j < 8; j++) {
            float mx = acc[0][j];
#pragma unroll
            for (int i = 1; i < 8; i++) mx = fmaxf(mx, acc[i][j]);
            mx = fmaxf(mx, __shfl_xor_sync(0xffffffffu, mx, 16));
            float s = 0.f;
#pragma unroll
            for (int i = 0; i < 8; i++) { acc[i][j] = __expf(acc[i][j] - mx); s += acc[i][j]; }
            s += __shfl_xor_sync(0xffffffffu, s, 16);
            float inv = 1.f / s;
#pragma unroll
            for (int i = 0; i < 8; i++) acc[i][j] *= inv;
        }
        const int tcol = (m0 >> 4) + (tid >> 5);   // t, constant per warp
#pragma unroll
        for (int i = 0; i < 8; i++) {
            int b = ((ty & 1) << 3) + i;
            float* orow = C + (size_t)b * (T_ * (size_t)V_) + (size_t)tcol * V_ + n0 + tx * 8;
            float4 o0, o1;
            o0.x = acc[i][0]; o0.y = acc[i][1]; o0.z = acc[i][2]; o0.w = acc[i][3];
            o1.x = acc[i][4]; o1.y = acc[i][5]; o1.z = acc[i][6]; o1.w = acc[i][7];
            *reinterpret_cast<float4*>(orow)     = o0;
            *reinterpret_cast<float4*>(orow + 4) = o1;
        }
    }
}

// =====================================================================
// Persistent LSTM recurrence, fence-free barrier.
// Identical math/layout to R9. Cross-CTA h exchange is L2-only
// (__stcg publish, __ldcg staging). Barrier = syncthreads -> tid0
// release-atomic arrive -> tid0 acquire-load spin -> syncthreads.
// NO __threadfence => no CCTL.IVALL => Wh stays L1-resident across
// all 127 steps.
// =====================================================================
__global__ __launch_bounds__(512, 1)
void lstm_persist(const float* __restrict__ Wh)
{
    __shared__ alignas(16) float hs[B_][512];
    __shared__ float gs[8][4][16];
    __shared__ float cs[16][8];

    const int tid = threadIdx.x;
    const int w   = tid >> 5, l = tid & 31;
    const int jj  = w & 7;
    const int o   = w >> 3;
    const int j   = blockIdx.x * 8 + jj;

    if (tid < 128) cs[tid >> 3][tid & 7] = 0.f;

    const ulonglong2* wrow[4];
#pragma unroll
    for (int g = 0; g < 4; g++)
        wrow[g] = reinterpret_cast<const ulonglong2*>(Wh + (size_t)(g * H_ + j) * H_);

    for (int t = 0; t < T_ - 1; t++) {
        unsigned long long acc[4][8];
#pragma unroll
        for (int g = 0; g < 4; g++)
#pragma unroll
            for (int b = 0; b < 8; b++) acc[g][b] = 0ull;

        const float4* hsrc = reinterpret_cast<const float4*>(g_hbuf[t & 1]);

        for (int half = 0; half < 2; half++) {
#pragma unroll
            for (int p = 0; p < 4; p++) {
                int e  = p * 512 + tid;
                int b  = e >> 7;
                int c4 = e & 127;
                float4 v = __ldcg(hsrc + (size_t)b * 256 + half * 128 + c4);
                *reinterpret_cast<float4*>(&hs[b][c4 * 4]) = v;
            }
            __syncthreads();
#pragma unroll
            for (int i = 0; i < 4; i++) {
                int kl = l * 4 + i * 128;
                int kg = half * 512 + kl;
                ulonglong2 wg[4];
#pragma unroll
                for (int g = 0; g < 4; g++) wg[g] = wrow[g][kg >> 2];
#pragma unroll
                for (int b = 0; b < 8; b++) {
                    ulonglong2 h2 = *reinterpret_cast<const ulonglong2*>(&hs[o * 8 + b][kl]);
#pragma unroll
                    for (int g = 0; g < 4; g++) {
                        fma2(acc[g][b], wg[g].x, h2.x);
                        fma2(acc[g][b], wg[g].y, h2.y);
                    }
                }
            }
            __syncthreads();
        }

#pragma unroll
        for (int g = 0; g < 4; g++)
#pragma unroll
            for (int b = 0; b < 8; b++) {
                float2 p2 = unpk(acc[g][b]);
                float s = p2.x + p2.y;
#pragma unroll
                for (int d = 16; d >= 1; d >>= 1)
                    s += __shfl_xor_sync(0xffffffffu, s, d);
                if (l == g * 8 + b) gs[jj][g][o * 8 + b] = s;
            }
        __syncthreads();

        if (tid < 128) {
            const int bq = tid >> 3, jq = tid & 7;
            const int jn = blockIdx.x * 8 + jq;
            const float* pre = g_Pre + (size_t)(t * 16 + bq) * FH;
            float Af = tanhf(gs[jq][0][bq] + pre[jn]);
            float Ag = tanhf(gs[jq][1][bq] + pre[1024 + jn]);
            float Ai = tanhf(gs[jq][2][bq] + pre[2048 + jn]);
            float Ao = tanhf(gs[jq][3][bq] + pre[3072 + jn]);
            float f  = sigf(Af);
            float gg = tanhf(Ag);
            float ii = sigf(Ai);
            float oo = sigf(Ao);
            float cold = cs[bq][jq];
            cs[bq][jq] = f * cold + gg * ii;
            float hn = oo * tanhf(cold);
            __stcg(&g_hbuf[(t + 1) & 1][bq * H_ + jn], hn);   // L2-only publish
            g_Hs[(size_t)(t + 1) * (B_ * H_) + bq * H_ + jn] = hn;
        }

        // fence-free grid barrier (release-arrive / acquire-spin)
        __syncthreads();                    // all CTA stores issued before arrive
        if (tid == 0) {
            unsigned int old;
            asm volatile("atom.add.release.gpu.u32 %0, [%1], %2;"
                         : "=r"(old) : "l"(&g_bar), "r"(1u) : "memory");
            const unsigned int target = 128u * (unsigned int)(t + 1);
            unsigned int cur;
            do {
                asm volatile("ld.acquire.gpu.u32 %0, [%1];"
                             : "=r"(cur) : "l"(&g_bar) : "memory");
                if (cur < target) __nanosleep(32);
            } while (cur < target);
        }
        __syncthreads();                    // propagate acquire CTA-wide
    }
}

__global__ void lstm_init()
{
    int e = blockIdx.x * blockDim.x + threadIdx.x;   // 0..32767
    if (e == 0) g_bar = 0u;
    reinterpret_cast<float*>(g_hbuf)[e] = 0.f;       // both h buffers
    if (e < B_ * H_) g_Hs[e] = 0.f;                  // Hs[0]
}

// =====================================================================
extern "C" void kernel_launch(void* const* d_in, const int* in_sizes, int n_in,
                              void* d_out, int out_size)
{
    const int*   idx   = (const int*)  d_in[0];
    const float* W_emb = (const float*)d_in[1];
    const float* Wx2   = (const float*)d_in[2];
    const float* Wh2   = (const float*)d_in[3];
    const float* b2    = (const float*)d_in[4];
    const float* Wa    = (const float*)d_in[5];
    const float* ba    = (const float*)d_in[6];
    float* out = (float*)d_out;
    (void)in_sizes; (void)n_in; (void)out_size;

    lstm_init<<<128, 256>>>();

    // Pre = gather(W_emb, idx) @ Wx2^T + b2   (rows m = t*16+b)
    sgemm<true, false><<<dim3(16, FH / 128), 256>>>(W_emb, Wx2, b2, idx, out);

    // whole recurrence in ONE persistent kernel (fence-free barriers)
    lstm_persist<<<128, 512>>>(Wh2);

    // V = Hs @ Wa^T + ba, fused softmax over batch axis -> out[b][t][v]
    sgemm<false, true><<<dim3(16, V_ / 128), 256>>>(W_emb, Wa, ba, idx, out);
}

// round 16
// speedup vs baseline: 1.1551x; 1.1042x over previous
#include <cuda_runtime.h>
#include <cstdint>

#define B_  16
#define T_  128
#define H_  1024
#define FH  4096
#define V_  32000
#define M_  2048   // B_*T_

// ---------------- device scratch (allocation-free) ----------------
__device__ float g_Pre[M_ * FH];      // 32 MB: X@Wx2^T + b2, rows m = t*16+b
__device__ float g_Hs [M_ * H_];      //  8 MB: emitted h, rows m = t*16+b
__device__ float g_hbuf[2][B_ * H_];  // double-buffered h (L2-only traffic)
__device__ unsigned int g_bar;        // grid barrier counter

__device__ __forceinline__ float sigf(float x) { return 1.f / (1.f + __expf(-x)); }

// ---------------- packed fp32x2 helpers ----------------
__device__ __forceinline__ unsigned long long pack2(float x, float y) {
    unsigned long long r;
    asm("mov.b64 %0, {%1, %2};" : "=l"(r) : "f"(x), "f"(y));
    return r;
}
__device__ __forceinline__ void fma2(unsigned long long& d,
                                     unsigned long long a, unsigned long long b) {
    asm("fma.rn.f32x2 %0, %1, %2, %0;" : "+l"(d) : "l"(a), "l"(b));
}
__device__ __forceinline__ float2 unpk(unsigned long long v) {
    float2 r;
    asm("mov.b64 {%0, %1}, %2;" : "=f"(r.x), "=f"(r.y) : "l"(v));
    return r;
}

// =====================================================================
// Tiled 128x128x16 SGEMM, C = A @ B^T + bias. 256 threads, 8x8 microtile,
// packed f32x2 inner product. Conflict-fixed column map: thread (ty,tx)
// owns rows ty*8..+7 and cols {tx*4+0..3, 64+tx*4+0..3} (16B-stride
// float4 B-reads -> full-bandwidth LDS, no 4-way bank conflicts).
//  GATHER : A row m is W_emb[idx[b*T_+t]] (m = t*16+b); writes g_Pre.
//  SOFTMAX: A = g_Hs; epilogue softmaxes each 16-row batch group (one
//           group per warp) and writes out[b][t][v].
// =====================================================================
template<bool GATHER, bool SOFTMAX>
__global__ __launch_bounds__(256, 2)
void sgemm(const float* __restrict__ A, const float* __restrict__ Bw,
           const float* __restrict__ bias, const int* __restrict__ idx,
           float* __restrict__ C)
{
    __shared__ alignas(16) float As[16][132];
    __shared__ alignas(16) float Bs[16][132];

    const int tid = threadIdx.x;
    const int ty  = tid >> 4, tx = tid & 15;
    const int m0  = blockIdx.x * 128;
    const int n0  = blockIdx.y * 128;

    const int r  = tid >> 1;
    const int lq = tid & 1;

    const float* arow;
    if (GATHER) {
        int m = m0 + r;
        int t = m >> 4, b = m & 15;
        arow = A + (size_t)idx[b * T_ + t] * H_;
    } else {
        arow = g_Hs + (size_t)(m0 + r) * H_;
    }
    const float* brow = Bw + (size_t)(n0 + r) * H_;

    unsigned long long acc2[8][4];
#pragma unroll
    for (int i = 0; i < 8; i++)
#pragma unroll
        for (int j = 0; j < 4; j++) acc2[i][j] = 0ull;

    for (int k0 = 0; k0 < H_; k0 += 16) {
#pragma unroll
        for (int p = 0; p < 2; p++) {
            int q = lq + 2 * p;
            float4 a4 = *reinterpret_cast<const float4*>(arow + k0 + q * 4);
            float4 b4 = *reinterpret_cast<const float4*>(brow + k0 + q * 4);
            As[q*4+0][r] = a4.x; As[q*4+1][r] = a4.y;
            As[q*4+2][r] = a4.z; As[q*4+3][r] = a4.w;
            Bs[q*4+0][r] = b4.x; Bs[q*4+1][r] = b4.y;
            Bs[q*4+2][r] = b4.z; Bs[q*4+3][r] = b4.w;
        }
        __syncthreads();
#pragma unroll
        for (int kk = 0; kk < 16; kk++) {
            float a[8];
            *reinterpret_cast<float4*>(&a[0]) = *reinterpret_cast<float4*>(&As[kk][ty*8]);
            *reinterpret_cast<float4*>(&a[4]) = *reinterpret_cast<float4*>(&As[kk][ty*8+4]);
            // cols tx*4..+3 and 64+tx*4..+3 : 16B-stride, conflict-free
            ulonglong2 u0 = *reinterpret_cast<ulonglong2*>(&Bs[kk][tx*4]);
            ulonglong2 u1 = *reinterpret_cast<ulonglong2*>(&Bs[kk][64 + tx*4]);
            unsigned long long bp[4] = {u0.x, u0.y, u1.x, u1.y};
#pragma unroll
            for (int i = 0; i < 8; i++) {
                unsigned long long ap = pack2(a[i], a[i]);
#pragma unroll
                for (int j = 0; j < 4; j++) fma2(acc2[i][j], ap, bp[j]);
            }
        }
        __syncthreads();
    }

    // unpack: acc[i][0..3] -> cols tx*4+j ; acc[i][4..7] -> cols 64+tx*4+(j-4)
    float acc[8][8];
#pragma unroll
    for (int i = 0; i < 8; i++)
#pragma unroll
        for (int j = 0; j < 4; j++) {
            float2 p = unpk(acc2[i][j]);
            acc[i][2*j] = p.x; acc[i][2*j+1] = p.y;
        }

    float bs[8];
#pragma unroll
    for (int j = 0; j < 4; j++) bs[j] = bias[n0 + tx*4 + j];
#pragma unroll
    for (int j = 4; j < 8; j++) bs[j] = bias[n0 + 64 + tx*4 + (j - 4)];

    if (!SOFTMAX) {
#pragma unroll
        for (int i = 0; i < 8; i++) {
            float* crow = g_Pre + (size_t)(m0 + ty * 8 + i) * FH + n0;
            float4 o0, o1;
            o0.x = acc[i][0]+bs[0]; o0.y = acc[i][1]+bs[1];
            o0.z = acc[i][2]+bs[2]; o0.w = acc[i][3]+bs[3];
            o1.x = acc[i][4]+bs[4]; o1.y = acc[i][5]+bs[5];
            o1.z = acc[i][6]+bs[6]; o1.w = acc[i][7]+bs[7];
            *reinterpret_cast<float4*>(crow + tx*4)      = o0;
            *reinterpret_cast<float4*>(crow + 64 + tx*4) = o1;
        }
    } else {
#pragma unroll
        for (int i = 0; i < 8; i++)
#pragma unroll
            for (int j = 0; j < 8; j++) acc[i][j] += bs[j];
        // softmax over 16-row batch group (rows of this warp-pair);
        // shfl 16 partner flips ty&1, same tx -> same columns. Unchanged.
#pragma unroll
        for (int j = 0; j < 8; j++) {
            float mx = acc[0][j];
#pragma unroll
            for (int i = 1; i < 8; i++) mx = fmaxf(mx, acc[i][j]);
            mx = fmaxf(mx, __shfl_xor_sync(0xffffffffu, mx, 16));
            float s = 0.f;
#pragma unroll
            for (int i = 0; i < 8; i++) { acc[i][j] = __expf(acc[i][j] - mx); s += acc[i][j]; }
            s += __shfl_xor_sync(0xffffffffu, s, 16);
            float inv = 1.f / s;
#pragma unroll
            for (int i = 0; i < 8; i++) acc[i][j] *= inv;
        }
        const int tcol = (m0 >> 4) + (tid >> 5);   // t, constant per warp
#pragma unroll
        for (int i = 0; i < 8; i++) {
            int b = ((ty & 1) << 3) + i;
            float* orow = C + (size_t)b * (T_ * (size_t)V_) + (size_t)tcol * V_ + n0;
            float4 o0, o1;
            o0.x = acc[i][0]; o0.y = acc[i][1]; o0.z = acc[i][2]; o0.w = acc[i][3];
            o1.x = acc[i][4]; o1.y = acc[i][5]; o1.z = acc[i][6]; o1.w = acc[i][7];
            *reinterpret_cast<float4*>(orow + tx*4)      = o0;
            *reinterpret_cast<float4*>(orow + 64 + tx*4) = o1;
        }
    }
}

// =====================================================================
// Persistent LSTM recurrence (R14, fence-free barrier, proven).
// =====================================================================
__global__ __launch_bounds__(512, 1)
void lstm_persist(const float* __restrict__ Wh)
{
    __shared__ alignas(16) float hs[B_][512];
    __shared__ float gs[8][4][16];
    __shared__ float cs[16][8];

    const int tid = threadIdx.x;
    const int w   = tid >> 5, l = tid & 31;
    const int jj  = w & 7;
    const int o   = w >> 3;
    const int j   = blockIdx.x * 8 + jj;

    if (tid < 128) cs[tid >> 3][tid & 7] = 0.f;

    const ulonglong2* wrow[4];
#pragma unroll
    for (int g = 0; g < 4; g++)
        wrow[g] = reinterpret_cast<const ulonglong2*>(Wh + (size_t)(g * H_ + j) * H_);

    for (int t = 0; t < T_ - 1; t++) {
        unsigned long long acc[4][8];
#pragma unroll
        for (int g = 0; g < 4; g++)
#pragma unroll
            for (int b = 0; b < 8; b++) acc[g][b] = 0ull;

        const float4* hsrc = reinterpret_cast<const float4*>(g_hbuf[t & 1]);

        for (int half = 0; half < 2; half++) {
#pragma unroll
            for (int p = 0; p < 4; p++) {
                int e  = p * 512 + tid;
                int b  = e >> 7;
                int c4 = e & 127;
                float4 v = __ldcg(hsrc + (size_t)b * 256 + half * 128 + c4);
                *reinterpret_cast<float4*>(&hs[b][c4 * 4]) = v;
            }
            __syncthreads();
#pragma unroll
            for (int i = 0; i < 4; i++) {
                int kl = l * 4 + i * 128;
                int kg = half * 512 + kl;
                ulonglong2 wg[4];
#pragma unroll
                for (int g = 0; g < 4; g++) wg[g] = wrow[g][kg >> 2];
#pragma unroll
                for (int b = 0; b < 8; b++) {
                    ulonglong2 h2 = *reinterpret_cast<const ulonglong2*>(&hs[o * 8 + b][kl]);
#pragma unroll
                    for (int g = 0; g < 4; g++) {
                        fma2(acc[g][b], wg[g].x, h2.x);
                        fma2(acc[g][b], wg[g].y, h2.y);
                    }
                }
            }
            __syncthreads();
        }

#pragma unroll
        for (int g = 0; g < 4; g++)
#pragma unroll
            for (int b = 0; b < 8; b++) {
                float2 p2 = unpk(acc[g][b]);
                float s = p2.x + p2.y;
#pragma unroll
                for (int d = 16; d >= 1; d >>= 1)
                    s += __shfl_xor_sync(0xffffffffu, s, d);
                if (l == g * 8 + b) gs[jj][g][o * 8 + b] = s;
            }
        __syncthreads();

        if (tid < 128) {
            const int bq = tid >> 3, jq = tid & 7;
            const int jn = blockIdx.x * 8 + jq;
            const float* pre = g_Pre + (size_t)(t * 16 + bq) * FH;
            float Af = tanhf(gs[jq][0][bq] + pre[jn]);
            float Ag = tanhf(gs[jq][1][bq] + pre[1024 + jn]);
            float Ai = tanhf(gs[jq][2][bq] + pre[2048 + jn]);
            float Ao = tanhf(gs[jq][3][bq] + pre[3072 + jn]);
            float f  = sigf(Af);
            float gg = tanhf(Ag);
            float ii = sigf(Ai);
            float oo = sigf(Ao);
            float cold = cs[bq][jq];
            cs[bq][jq] = f * cold + gg * ii;
            float hn = oo * tanhf(cold);
            __stcg(&g_hbuf[(t + 1) & 1][bq * H_ + jn], hn);
            g_Hs[(size_t)(t + 1) * (B_ * H_) + bq * H_ + jn] = hn;
        }

        __syncthreads();
        if (tid == 0) {
            unsigned int old;
            asm volatile("atom.add.release.gpu.u32 %0, [%1], %2;"
                         : "=r"(old) : "l"(&g_bar), "r"(1u) : "memory");
            const unsigned int target = 128u * (unsigned int)(t + 1);
            unsigned int cur;
            do {
                asm volatile("ld.acquire.gpu.u32 %0, [%1];"
                             : "=r"(cur) : "l"(&g_bar) : "memory");
                if (cur < target) __nanosleep(32);
            } while (cur < target);
        }
        __syncthreads();
    }
}

__global__ void lstm_init()
{
    int e = blockIdx.x * blockDim.x + threadIdx.x;   // 0..32767
    if (e == 0) g_bar = 0u;
    reinterpret_cast<float*>(g_hbuf)[e] = 0.f;       // both h buffers
    if (e < B_ * H_) g_Hs[e] = 0.f;                  // Hs[0]
}

// =====================================================================
extern "C" void kernel_launch(void* const* d_in, const int* in_sizes, int n_in,
                              void* d_out, int out_size)
{
    const int*   idx   = (const int*)  d_in[0];
    const float* W_emb = (const float*)d_in[1];
    const float* Wx2   = (const float*)d_in[2];
    const float* Wh2   = (const float*)d_in[3];
    const float* b2    = (const float*)d_in[4];
    const float* Wa    = (const float*)d_in[5];
    const float* ba    = (const float*)d_in[6];
    float* out = (float*)d_out;
    (void)in_sizes; (void)n_in; (void)out_size;

    lstm_init<<<128, 256>>>();

    // Pre = gather(W_emb, idx) @ Wx2^T + b2   (rows m = t*16+b)
    sgemm<true, false><<<dim3(16, FH / 128), 256>>>(W_emb, Wx2, b2, idx, out);

    // whole recurrence in ONE persistent kernel (fence-free barriers)
    lstm_persist<<<128, 512>>>(Wh2);

    // V = Hs @ Wa^T + ba, fused softmax over batch axis -> out[b][t][v]
    sgemm<false, true><<<dim3(16, V_ / 128), 256>>>(W_emb, Wa, ba, idx, out);
}

// round 17
// speedup vs baseline: 1.3004x; 1.1258x over previous
#include <cuda_runtime.h>
#include <cstdint>

#define B_  16
#define T_  128
#define H_  1024
#define FH  4096
#define V_  32000
#define M_  2048   // B_*T_

// ---------------- device scratch (allocation-free) ----------------
__device__ float g_Pre[M_ * FH];      // 32 MB: X@Wx2^T + b2, rows m = t*16+b
__device__ float g_Hs [M_ * H_];      //  8 MB: emitted h, rows m = t*16+b
__device__ float g_hbuf[2][B_ * H_];  // double-buffered h (L2-only traffic)
__device__ unsigned int g_bar;        // grid barrier counter

__device__ __forceinline__ float sigf(float x) { return 1.f / (1.f + __expf(-x)); }

// ---------------- packed fp32x2 helpers ----------------
__device__ __forceinline__ unsigned long long pack2(float x, float y) {
    unsigned long long r;
    asm("mov.b64 %0, {%1, %2};" : "=l"(r) : "f"(x), "f"(y));
    return r;
}
__device__ __forceinline__ void fma2(unsigned long long& d,
                                     unsigned long long a, unsigned long long b) {
    asm("fma.rn.f32x2 %0, %1, %2, %0;" : "+l"(d) : "l"(a), "l"(b));
}
__device__ __forceinline__ float2 unpk(unsigned long long v) {
    float2 r;
    asm("mov.b64 {%0, %1}, %2;" : "=f"(r.x), "=f"(r.y) : "l"(v));
    return r;
}

// =====================================================================
// Tiled 128x128x16 SGEMM, C = A @ B^T + bias. 256 threads, 8x8 microtile,
// packed f32x2 inner product. Conflict-fixed column map (R16): thread
// (ty,tx) owns rows ty*8..+7, cols {tx*4+0..3, 64+tx*4+0..3}.
// R17: DOUBLE-BUFFERED smem — prefetch chunk c+1 into registers while
// computing chunk c; one __syncthreads per chunk (was two) and the
// L2 load latency is hidden behind the 512 fma2 of the current chunk.
//  GATHER : A row m is W_emb[idx[b*T_+t]] (m = t*16+b); writes g_Pre.
//  SOFTMAX: A = g_Hs; epilogue softmaxes each 16-row batch group.
// =====================================================================
template<bool GATHER, bool SOFTMAX>
__global__ __launch_bounds__(256, 2)
void sgemm(const float* __restrict__ A, const float* __restrict__ Bw,
           const float* __restrict__ bias, const int* __restrict__ idx,
           float* __restrict__ C)
{
    __shared__ alignas(16) float As[2][16][132];
    __shared__ alignas(16) float Bs[2][16][132];

    const int tid = threadIdx.x;
    const int ty  = tid >> 4, tx = tid & 15;
    const int m0  = blockIdx.x * 128;
    const int n0  = blockIdx.y * 128;

    const int r  = tid >> 1;     // load-role row
    const int lq = tid & 1;

    const float* arow;
    if (GATHER) {
        int m = m0 + r;
        int t = m >> 4, b = m & 15;
        arow = A + (size_t)idx[b * T_ + t] * H_;
    } else {
        arow = g_Hs + (size_t)(m0 + r) * H_;
    }
    const float* brow = Bw + (size_t)(n0 + r) * H_;

    unsigned long long acc2[8][4];
#pragma unroll
    for (int i = 0; i < 8; i++)
#pragma unroll
        for (int j = 0; j < 4; j++) acc2[i][j] = 0ull;

    float4 a4[2], b4[2];

    // prologue: chunk 0 -> buffer 0
#pragma unroll
    for (int p = 0; p < 2; p++) {
        int q = lq + 2 * p;
        a4[p] = *reinterpret_cast<const float4*>(arow + q * 4);
        b4[p] = *reinterpret_cast<const float4*>(brow + q * 4);
    }
#pragma unroll
    for (int p = 0; p < 2; p++) {
        int q = lq + 2 * p;
        As[0][q*4+0][r] = a4[p].x; As[0][q*4+1][r] = a4[p].y;
        As[0][q*4+2][r] = a4[p].z; As[0][q*4+3][r] = a4[p].w;
        Bs[0][q*4+0][r] = b4[p].x; Bs[0][q*4+1][r] = b4[p].y;
        Bs[0][q*4+2][r] = b4[p].z; Bs[0][q*4+3][r] = b4[p].w;
    }
    __syncthreads();

    for (int c = 0; c < H_ / 16; c++) {
        const int cur = c & 1;

        if (c < H_ / 16 - 1) {
            const int k0n = (c + 1) * 16;
#pragma unroll
            for (int p = 0; p < 2; p++) {
                int q = lq + 2 * p;
                a4[p] = *reinterpret_cast<const float4*>(arow + k0n + q * 4);
                b4[p] = *reinterpret_cast<const float4*>(brow + k0n + q * 4);
            }
        }

#pragma unroll
        for (int kk = 0; kk < 16; kk++) {
            float a[8];
            *reinterpret_cast<float4*>(&a[0]) = *reinterpret_cast<float4*>(&As[cur][kk][ty*8]);
            *reinterpret_cast<float4*>(&a[4]) = *reinterpret_cast<float4*>(&As[cur][kk][ty*8+4]);
            ulonglong2 u0 = *reinterpret_cast<ulonglong2*>(&Bs[cur][kk][tx*4]);
            ulonglong2 u1 = *reinterpret_cast<ulonglong2*>(&Bs[cur][kk][64 + tx*4]);
            unsigned long long bp[4] = {u0.x, u0.y, u1.x, u1.y};
#pragma unroll
            for (int i = 0; i < 8; i++) {
                unsigned long long ap = pack2(a[i], a[i]);
#pragma unroll
                for (int j = 0; j < 4; j++) fma2(acc2[i][j], ap, bp[j]);
            }
        }

        if (c < H_ / 16 - 1) {
            const int nxt = cur ^ 1;
#pragma unroll
            for (int p = 0; p < 2; p++) {
                int q = lq + 2 * p;
                As[nxt][q*4+0][r] = a4[p].x; As[nxt][q*4+1][r] = a4[p].y;
                As[nxt][q*4+2][r] = a4[p].z; As[nxt][q*4+3][r] = a4[p].w;
                Bs[nxt][q*4+0][r] = b4[p].x; Bs[nxt][q*4+1][r] = b4[p].y;
                Bs[nxt][q*4+2][r] = b4[p].z; Bs[nxt][q*4+3][r] = b4[p].w;
            }
            __syncthreads();
        }
    }

    // unpack: acc[i][0..3] -> cols tx*4+j ; acc[i][4..7] -> 64+tx*4+(j-4)
    float acc[8][8];
#pragma unroll
    for (int i = 0; i < 8; i++)
#pragma unroll
        for (int j = 0; j < 4; j++) {
            float2 p = unpk(acc2[i][j]);
            acc[i][2*j] = p.x; acc[i][2*j+1] = p.y;
        }

    float bs[8];
#pragma unroll
    for (int j = 0; j < 4; j++) bs[j] = bias[n0 + tx*4 + j];
#pragma unroll
    for (int j = 4; j < 8; j++) bs[j] = bias[n0 + 64 + tx*4 + (j - 4)];

    if (!SOFTMAX) {
#pragma unroll
        for (int i = 0; i < 8; i++) {
            float* crow = g_Pre + (size_t)(m0 + ty * 8 + i) * FH + n0;
            float4 o0, o1;
            o0.x = acc[i][0]+bs[0]; o0.y = acc[i][1]+bs[1];
            o0.z = acc[i][2]+bs[2]; o0.w = acc[i][3]+bs[3];
            o1.x = acc[i][4]+bs[4]; o1.y = acc[i][5]+bs[5];
            o1.z = acc[i][6]+bs[6]; o1.w = acc[i][7]+bs[7];
            *reinterpret_cast<float4*>(crow + tx*4)      = o0;
            *reinterpret_cast<float4*>(crow + 64 + tx*4) = o1;
        }
    } else {
#pragma unroll
        for (int i = 0; i < 8; i++)
#pragma unroll
            for (int j = 0; j < 8; j++) acc[i][j] += bs[j];
        // softmax over 16-row batch group (warp-pair rows; shfl 16
        // partner flips ty&1, same tx -> same columns).
#pragma unroll
        for (int j = 0; j < 8; j++) {
            float mx = acc[0][j];
#pragma unroll
            for (int i = 1; i < 8; i++) mx = fmaxf(mx, acc[i][j]);
            mx = fmaxf(mx, __shfl_xor_sync(0xffffffffu, mx, 16));
            float s = 0.f;
#pragma unroll
            for (int i = 0; i < 8; i++) { acc[i][j] = __expf(acc[i][j] - mx); s += acc[i][j]; }
            s += __shfl_xor_sync(0xffffffffu, s, 16);
            float inv = 1.f / s;
#pragma unroll
            for (int i = 0; i < 8; i++) acc[i][j] *= inv;
        }
        const int tcol = (m0 >> 4) + (tid >> 5);   // t, constant per warp
#pragma unroll
        for (int i = 0; i < 8; i++) {
            int b = ((ty & 1) << 3) + i;
            float* orow = C + (size_t)b * (T_ * (size_t)V_) + (size_t)tcol * V_ + n0;
            float4 o0, o1;
            o0.x = acc[i][0]; o0.y = acc[i][1]; o0.z = acc[i][2]; o0.w = acc[i][3];
            o1.x = acc[i][4]; o1.y = acc[i][5]; o1.z = acc[i][6]; o1.w = acc[i][7];
            *reinterpret_cast<float4*>(orow + tx*4)      = o0;
            *reinterpret_cast<float4*>(orow + 64 + tx*4) = o1;
        }
    }
}

// =====================================================================
// Persistent LSTM recurrence (R14, fence-free barrier, proven).
// =====================================================================
__global__ __launch_bounds__(512, 1)
void lstm_persist(const float* __restrict__ Wh)
{
    __shared__ alignas(16) float hs[B_][512];
    __shared__ float gs[8][4][16];
    __shared__ float cs[16][8];

    const int tid = threadIdx.x;
    const int w   = tid >> 5, l = tid & 31;
    const int jj  = w & 7;
    const int o   = w >> 3;
    const int j   = blockIdx.x * 8 + jj;

    if (tid < 128) cs[tid >> 3][tid & 7] = 0.f;

    const ulonglong2* wrow[4];
#pragma unroll
    for (int g = 0; g < 4; g++)
        wrow[g] = reinterpret_cast<const ulonglong2*>(Wh + (size_t)(g * H_ + j) * H_);

    for (int t = 0; t < T_ - 1; t++) {
        unsigned long long acc[4][8];
#pragma unroll
        for (int g = 0; g < 4; g++)
#pragma unroll
            for (int b = 0; b < 8; b++) acc[g][b] = 0ull;

        const float4* hsrc = reinterpret_cast<const float4*>(g_hbuf[t & 1]);

        for (int half = 0; half < 2; half++) {
#pragma unroll
            for (int p = 0; p < 4; p++) {
                int e  = p * 512 + tid;
                int b  = e >> 7;
                int c4 = e & 127;
                float4 v = __ldcg(hsrc + (size_t)b * 256 + half * 128 + c4);
                *reinterpret_cast<float4*>(&hs[b][c4 * 4]) = v;
            }
            __syncthreads();
#pragma unroll
            for (int i = 0; i < 4; i++) {
                int kl = l * 4 + i * 128;
                int kg = half * 512 + kl;
                ulonglong2 wg[4];
#pragma unroll
                for (int g = 0; g < 4; g++) wg[g] = wrow[g][kg >> 2];
#pragma unroll
                for (int b = 0; b < 8; b++) {
                    ulonglong2 h2 = *reinterpret_cast<const ulonglong2*>(&hs[o * 8 + b][kl]);
#pragma unroll
                    for (int g = 0; g < 4; g++) {
                        fma2(acc[g][b], wg[g].x, h2.x);
                        fma2(acc[g][b], wg[g].y, h2.y);
                    }
                }
            }
            __syncthreads();
        }

#pragma unroll
        for (int g = 0; g < 4; g++)
#pragma unroll
            for (int b = 0; b < 8; b++) {
                float2 p2 = unpk(acc[g][b]);
                float s = p2.x + p2.y;
#pragma unroll
                for (int d = 16; d >= 1; d >>= 1)
                    s += __shfl_xor_sync(0xffffffffu, s, d);
                if (l == g * 8 + b) gs[jj][g][o * 8 + b] = s;
            }
        __syncthreads();

        if (tid < 128) {
            const int bq = tid >> 3, jq = tid & 7;
            const int jn = blockIdx.x * 8 + jq;
            const float* pre = g_Pre + (size_t)(t * 16 + bq) * FH;
            float Af = tanhf(gs[jq][0][bq] + pre[jn]);
            float Ag = tanhf(gs[jq][1][bq] + pre[1024 + jn]);
            float Ai = tanhf(gs[jq][2][bq] + pre[2048 + jn]);
            float Ao = tanhf(gs[jq][3][bq] + pre[3072 + jn]);
            float f  = sigf(Af);
            float gg = tanhf(Ag);
            float ii = sigf(Ai);
            float oo = sigf(Ao);
            float cold = cs[bq][jq];
            cs[bq][jq] = f * cold + gg * ii;
            float hn = oo * tanhf(cold);
            __stcg(&g_hbuf[(t + 1) & 1][bq * H_ + jn], hn);
            g_Hs[(size_t)(t + 1) * (B_ * H_) + bq * H_ + jn] = hn;
        }

        __syncthreads();
        if (tid == 0) {
            unsigned int old;
            asm volatile("atom.add.release.gpu.u32 %0, [%1], %2;"
                         : "=r"(old) : "l"(&g_bar), "r"(1u) : "memory");
            const unsigned int target = 128u * (unsigned int)(t + 1);
            unsigned int cur;
            do {
                asm volatile("ld.acquire.gpu.u32 %0, [%1];"
                             : "=r"(cur) : "l"(&g_bar) : "memory");
                if (cur < target) __nanosleep(32);
            } while (cur < target);
        }
        __syncthreads();
    }
}

__global__ void lstm_init()
{
    int e = blockIdx.x * blockDim.x + threadIdx.x;   // 0..32767
    if (e == 0) g_bar = 0u;
    reinterpret_cast<float*>(g_hbuf)[e] = 0.f;       // both h buffers
    if (e < B_ * H_) g_Hs[e] = 0.f;                  // Hs[0]
}

// =====================================================================
extern "C" void kernel_launch(void* const* d_in, const int* in_sizes, int n_in,
                              void* d_out, int out_size)
{
    const int*   idx   = (const int*)  d_in[0];
    const float* W_emb = (const float*)d_in[1];
    const float* Wx2   = (const float*)d_in[2];
    const float* Wh2   = (const float*)d_in[3];
    const float* b2    = (const float*)d_in[4];
    const float* Wa    = (const float*)d_in[5];
    const float* ba    = (const float*)d_in[6];
    float* out = (float*)d_out;
    (void)in_sizes; (void)n_in; (void)out_size;

    lstm_init<<<128, 256>>>();

    // Pre = gather(W_emb, idx) @ Wx2^T + b2   (rows m = t*16+b)
    sgemm<true, false><<<dim3(16, FH / 128), 256>>>(W_emb, Wx2, b2, idx, out);

    // whole recurrence in ONE persistent kernel (fence-free barriers)
    lstm_persist<<<128, 512>>>(Wh2);

    // V = Hs @ Wa^T + ba, fused softmax over batch axis -> out[b][t][v]
    sgemm<false, true><<<dim3(16, V_ / 128), 256>>>(W_emb, Wa, ba, idx, out);
}